// round 13
// baseline (speedup 1.0000x reference)
#include <cuda_runtime.h>
#include <cstdint>
#include <cfloat>

// Problem constants (fixed by the dataset)
constexpr int Bv  = 16;      // batch
constexpr int Nv  = 16384;   // pixels
constexpr int Dv  = 64;      // embed dim
constexpr int D4v = 16;      // float4 chunks per vector
constexpr int D4H = 8;       // float4 chunks per d-half
constexpr int Kv  = 64;      // templates
constexpr int WPB = 4;       // warps per block = pixels per block
constexpr float EPS = 1e-3f; // near-tie margin (>> fp32 dist error ~1e-5)

using ull = unsigned long long;

// ---- packed f32x2 helpers (per-lane rounding identical to fmaf) ----
__device__ __forceinline__ ull f2_fma(ull a, ull b, ull c) {
    ull d;
    asm("fma.rn.f32x2 %0, %1, %2, %3;" : "=l"(d) : "l"(a), "l"(b), "l"(c));
    return d;
}
__device__ __forceinline__ void f2_unpack(ull p, float& lo, float& hi) {
    unsigned a, b;
    asm("mov.b64 {%0, %1}, %2;" : "=r"(a), "=r"(b) : "l"(p));
    lo = __uint_as_float(a); hi = __uint_as_float(b);
}

// XOR swizzles within an 8-chunk half (conflict-free per 8-lane phase for
// staging and for the main loop's k=r+8j / b=c+4i access octets)
__device__ __forceinline__ int tswh(int k, int d) { return k * 8 + (d ^ (k & 7)); }
__device__ __forceinline__ int xswh(int b, int d) { return b * 8 + (d ^ (b & 7)); }

struct Pix {                              // 10880 B per pixel
    float4 ts[Kv * D4H];                  // 8 KB t half-tile (swizzled)
    float4 xs[Bv * D4H];                  // 2 KB x half-tile (swizzled)
    float  t2s[Kv];
    float  x2s[Bv];
    float  bestv[Bv];
    int    bestk[Bv];
    int    cnt[Bv];
    ull    refined[Bv];
};

__global__ __launch_bounds__(32 * WPB, 4)
void osc_kernel(const float4* __restrict__ xg,     // frame_embeddings [B,N,D] f32
                const float4* __restrict__ tg,     // templates        [K,N,D] f32
                const int*    __restrict__ tcls,   // template_classes [K] int32
                float* __restrict__ out)
{
    __shared__ Pix   pix[WPB];
    __shared__ float clsf[Kv];
    __shared__ float obuf[4 * Bv * WPB];  // [out][b][pixel]

    const int tid  = threadIdx.x;
    const int w    = tid >> 5;            // warp = pixel slot
    const int lane = tid & 31;
    const int n0   = blockIdx.x * WPB;
    const int n    = n0 + w;
    Pix& P = pix[w];

    if (tid < Kv) clsf[tid] = (float)tcls[tid];
    if (lane < Bv) {
        P.cnt[lane]     = 0;
        P.refined[lane] = 0xFFFFFFFFFFFFFFFFULL;
    }

    // tile coords: b in {c, c+4, c+8, c+12}; k in {r+8j, j=0..7}
    const int c = lane & 3;
    const int r = lane >> 2;

    ull acc2[4][8];                       // (even,odd)-pair dot partials
#pragma unroll
    for (int i = 0; i < 4; ++i)
#pragma unroll
        for (int j = 0; j < 8; ++j) acc2[i][j] = 0ULL;
    ull acct2[8];                         // folded t-norms (published by c==0)
#pragma unroll
    for (int j = 0; j < 8; ++j) acct2[j] = 0ULL;
    ull accx2[4];                         // folded x-norms (published by r==0)
#pragma unroll
    for (int i = 0; i < 4; ++i) accx2[i] = 0ULL;

    // ---- two d-halves; warp-local sync only ----
#pragma unroll 1
    for (int h = 0; h < 2; ++h) {
        __syncwarp();                     // prior half fully consumed
        // stage t half: 512 float4 / 32 lanes = 16 each (bounded unroll)
#pragma unroll 4
        for (int i = 0; i < 16; ++i) {
            int idx = lane + i * 32;
            int k   = idx >> 3;
            int d   = idx & 7;
            P.ts[tswh(k, d)] = tg[((size_t)k * Nv + n) * D4v + h * D4H + d];
        }
        // stage x half: 128 float4 / 32 lanes = 4 each
#pragma unroll
        for (int i = 0; i < 4; ++i) {
            int idx = lane + i * 32;
            int b   = idx >> 3;
            int d   = idx & 7;
            P.xs[xswh(b, d)] = xg[((size_t)b * Nv + n) * D4v + h * D4H + d];
        }
        __syncwarp();

        // main loop over this half's 8 chunks
#pragma unroll
        for (int d = 0; d < D4H; ++d) {
            ulonglong2 xv[4];
#pragma unroll
            for (int i = 0; i < 4; ++i) {
                xv[i] = *reinterpret_cast<const ulonglong2*>(&P.xs[xswh(c + 4 * i, d)]);
                accx2[i] = f2_fma(xv[i].x, xv[i].x, accx2[i]);
                accx2[i] = f2_fma(xv[i].y, xv[i].y, accx2[i]);
            }
#pragma unroll
            for (int j = 0; j < 8; ++j) {
                const ulonglong2 tv =
                    *reinterpret_cast<const ulonglong2*>(&P.ts[tswh(r + 8 * j, d)]);
                acct2[j] = f2_fma(tv.x, tv.x, acct2[j]);
                acct2[j] = f2_fma(tv.y, tv.y, acct2[j]);
#pragma unroll
                for (int i = 0; i < 4; ++i) {
                    acc2[i][j] = f2_fma(xv[i].x, tv.x, acc2[i][j]);
                    acc2[i][j] = f2_fma(xv[i].y, tv.y, acc2[i][j]);
                }
            }
        }
    }

    // ---- publish norms ----
    if (c == 0) {
#pragma unroll
        for (int j = 0; j < 8; ++j) {
            float lo, hi; f2_unpack(acct2[j], lo, hi);
            P.t2s[r + 8 * j] = lo + hi;
        }
    }
    if (r == 0) {
#pragma unroll
        for (int i = 0; i < 4; ++i) {
            float lo, hi; f2_unpack(accx2[i], lo, hi);
            P.x2s[c + 4 * i] = lo + hi;
        }
    }
    __syncwarp();

    // ---- distances + per-thread min over its 8 k's per b ----
    float df[4][8];
    float bv[4];
    int   bk[4];
#pragma unroll
    for (int i = 0; i < 4; ++i) {
        const float bx2 = P.x2s[c + 4 * i];
        bv[i] = FLT_MAX; bk[i] = Kv;
#pragma unroll
        for (int j = 0; j < 8; ++j) {
            const int k = r + 8 * j;
            float lo, hi; f2_unpack(acc2[i][j], lo, hi);
            const float d = bx2 + P.t2s[k] - 2.0f * (lo + hi);
            df[i][j] = d;
            if (d < bv[i]) { bv[i] = d; bk[i] = k; }   // j asc == k asc: first-min
        }
    }

    // ---- shuffle reduce across the 8 r-groups (lanes sharing c) ----
#pragma unroll
    for (int m = 4; m <= 16; m <<= 1) {
#pragma unroll
        for (int i = 0; i < 4; ++i) {
            const float ov = __shfl_xor_sync(0xFFFFFFFFu, bv[i], m);
            const int   ok = __shfl_xor_sync(0xFFFFFFFFu, bk[i], m);
            if (ov < bv[i] || (ov == bv[i] && ok < bk[i])) { bv[i] = ov; bk[i] = ok; }
        }
    }
    if (r == 0) {
#pragma unroll
        for (int i = 0; i < 4; ++i) {
            P.bestv[c + 4 * i] = bv[i];
            P.bestk[c + 4 * i] = bk[i];
        }
    }
    __syncwarp();

    // ---- near-tie candidate count per b ----
#pragma unroll
    for (int i = 0; i < 4; ++i) {
        const int b = c + 4 * i;
        const float lim = P.bestv[b] + EPS;
        int local = 0;
#pragma unroll
        for (int j = 0; j < 8; ++j) local += (df[i][j] <= lim) ? 1 : 0;
        if (local) atomicAdd(&P.cnt[b], local);
    }
    __syncwarp();

    // ---- Phase B (RARE): exact fp64 refinement; rows re-read from gmem ----
#pragma unroll 1
    for (int i = 0; i < 4; ++i) {
        const int b = c + 4 * i;
        if (P.cnt[b] < 2) continue;                   // uncontested: skip fp64
        const float lim = P.bestv[b] + EPS;
#pragma unroll 1
        for (int j = 0; j < 8; ++j) {
            if (df[i][j] > lim) continue;
            const int k = r + 8 * j;
            const float4* xrow = &xg[((size_t)b * Nv + n) * D4v];
            const float4* trow = &tg[((size_t)k * Nv + n) * D4v];
            double dd = 0.0;
#pragma unroll 1
            for (int d4 = 0; d4 < D4v; ++d4) {
                const float4 xv = __ldg(xrow + d4);
                const float4 tv = __ldg(trow + d4);
                const double e0 = (double)xv.x - (double)tv.x;
                const double e1 = (double)xv.y - (double)tv.y;
                const double e2 = (double)xv.z - (double)tv.z;
                const double e3 = (double)xv.w - (double)tv.w;
                dd = fma(e0, e0, dd); dd = fma(e1, e1, dd);
                dd = fma(e2, e2, dd); dd = fma(e3, e3, dd);
            }
            const float dfx = (float)dd;              // exact -> fp32
            const ull key = ((ull)__float_as_uint(dfx) << 6) | (ull)k;
            atomicMin(&P.refined[b], key);
        }
    }
    __syncwarp();

    // ---- finalize per b into obuf ----
    if (lane < Bv) {
        float fbv;
        int   fbk;
        if (P.cnt[lane] >= 2) {
            const ull key = P.refined[lane];
            fbk = (int)(key & 63ULL);
            fbv = __uint_as_float((unsigned)(key >> 6));
        } else {
            fbv = P.bestv[lane];
            fbk = P.bestk[lane];
        }
        obuf[(0 * Bv + lane) * WPB + w] = (fbv <= 0.5f) ? 1.0f : 0.0f;
        obuf[(1 * Bv + lane) * WPB + w] = (fbv <= 1.0f) ? 1.0f : 0.0f;
        obuf[(2 * Bv + lane) * WPB + w] = fbv;
        obuf[(3 * Bv + lane) * WPB + w] = clsf[fbk];
    }
    __syncthreads();

    // ---- block epilogue: float4 stores (4 consecutive pixels wide) ----
    if (tid < 4 * Bv) {
        const int o = tid >> 4;
        const int b = tid & 15;
        const size_t BN = (size_t)Bv * Nv;
        const float4 v = *reinterpret_cast<const float4*>(&obuf[(o * Bv + b) * WPB]);
        *reinterpret_cast<float4*>(&out[(size_t)o * BN + (size_t)b * Nv + n0]) = v;
    }
}

extern "C" void kernel_launch(void* const* d_in, const int* in_sizes, int n_in,
                              void* d_out, int out_size)
{
    const float4* frame = (const float4*)d_in[0];   // [16,16384,64] f32
    const float4* tmpl  = (const float4*)d_in[1];   // [64,16384,64] f32
    const int*    tcls  = (const int*)d_in[2];      // [64] int32
    float*        out   = (float*)d_out;

    osc_kernel<<<Nv / WPB, 32 * WPB>>>(frame, tmpl, tcls, out);
}

// round 14
// speedup vs baseline: 1.2016x; 1.2016x over previous
#include <cuda_runtime.h>
#include <cstdint>
#include <cfloat>

// Problem constants (fixed by the dataset)
constexpr int Bv  = 16;      // batch
constexpr int Nv  = 16384;   // pixels
constexpr int Dv  = 64;      // embed dim
constexpr int D4v = 16;      // float4 chunks per vector
constexpr int Kv  = 64;      // templates
constexpr int PPB = 2;       // pixels per block (warp-pair each -> all 4 SMSPs)
constexpr float EPS = 1e-3f; // near-tie margin (>> fp32 dist error ~1e-5)

using ull = unsigned long long;

// ---- packed f32x2 helpers (per-lane rounding identical to fmaf) ----
__device__ __forceinline__ ull f2_fma(ull a, ull b, ull c) {
    ull d;
    asm("fma.rn.f32x2 %0, %1, %2, %3;" : "=l"(d) : "l"(a), "l"(b), "l"(c));
    return d;
}
__device__ __forceinline__ void f2_unpack(ull p, float& lo, float& hi) {
    unsigned a, b;
    asm("mov.b64 {%0, %1}, %2;" : "=r"(a), "=r"(b) : "l"(p));
    lo = __uint_as_float(a); hi = __uint_as_float(b);
}

// XOR swizzle (conflict-free per 8-lane phase for all our access patterns)
__device__ __forceinline__ int tsw(int k, int d4) { return k * 16 + (d4 ^ (k & 7)); }
__device__ __forceinline__ int xsw(int b, int d4) { return b * 16 + (d4 ^ (b & 7)); }

__global__ __launch_bounds__(128, 5)
void osc_kernel(const float4* __restrict__ xg,     // frame_embeddings [B,N,D] f32
                const float4* __restrict__ tg,     // templates        [K,N,D] f32
                const int*    __restrict__ tcls,   // template_classes [K] int32
                float* __restrict__ out)
{
    __shared__ __align__(16) float4 ts[PPB][Kv * 16];  // template tiles (swizzled)
    __shared__ __align__(16) float4 xs[PPB][Bv * 16];  // frame tiles (swizzled)
    __shared__ float t2s[PPB][Kv];
    __shared__ float x2s[PPB][Bv];
    __shared__ float clsf[Kv];
    __shared__ float rv2[PPB][2][Bv];                  // per-warp partial minima
    __shared__ int   ri2[PPB][2][Bv];
    __shared__ float bestvs[PPB][Bv];
    __shared__ int   bestks[PPB][Bv];
    __shared__ int   cnt[PPB][Bv];
    __shared__ ull   refined[PPB][Bv];
    __shared__ float fin_v[PPB][Bv];
    __shared__ float fin_cls[PPB][Bv];

    const int tid = threadIdx.x;
    const int p   = tid >> 6;            // pixel slot 0/1 (warps 0,1 | 2,3)
    const int q   = tid & 63;            // thread id within pixel
    const int n0  = blockIdx.x * PPB;
    const int n   = n0 + p;

    // ---- stage tiles (each pixel's 64 threads; coalesced 512B per warp) ----
#pragma unroll
    for (int i = 0; i < 16; ++i) {
        int idx = q + i * 64;            // 1024 float4
        int k   = idx >> 4;
        int d4  = idx & 15;
        ts[p][tsw(k, d4)] = tg[((size_t)k * Nv + n) * D4v + d4];
    }
#pragma unroll
    for (int i = 0; i < 4; ++i) {
        int idx = q + i * 64;            // 256 float4
        int b   = idx >> 4;
        int d4  = idx & 15;
        xs[p][xsw(b, d4)] = xg[((size_t)b * Nv + n) * D4v + d4];
    }
    if (tid < Kv) clsf[tid] = (float)tcls[tid];
    if (q < Bv) {
        cnt[p][q]     = 0;
        refined[p][q] = 0xFFFFFFFFFFFFFFFFULL;
    }
    __syncthreads();

    // ---- norms: ||t_k||^2 (one row per thread), ||x_b||^2 (q<16) ----
    {
        float s0 = 0.f, s1 = 0.f, s2 = 0.f, s3 = 0.f;
#pragma unroll
        for (int d4 = 0; d4 < D4v; ++d4) {
            float4 v = ts[p][tsw(q, d4)];
            s0 = fmaf(v.x, v.x, s0); s1 = fmaf(v.y, v.y, s1);
            s2 = fmaf(v.z, v.z, s2); s3 = fmaf(v.w, v.w, s3);
        }
        t2s[p][q] = (s0 + s1) + (s2 + s3);
    }
    if (q < Bv) {
        float s0 = 0.f, s1 = 0.f, s2 = 0.f, s3 = 0.f;
#pragma unroll
        for (int d4 = 0; d4 < D4v; ++d4) {
            float4 v = xs[p][xsw(q, d4)];
            s0 = fmaf(v.x, v.x, s0); s1 = fmaf(v.y, v.y, s1);
            s2 = fmaf(v.z, v.z, s2); s3 = fmaf(v.w, v.w, s3);
        }
        x2s[p][q] = (s0 + s1) + (s2 + s3);
    }
    __syncthreads();

    // ---- Phase A: 4x4 register-tile dot products, packed f32x2 over d ----
    // thread covers b in {c, c+4, c+8, c+12}, k in {r, r+16, r+32, r+48}
    const int c = q & 3;
    const int r = q >> 2;

    ull acc2[4][4];
#pragma unroll
    for (int i = 0; i < 4; ++i)
#pragma unroll
        for (int j = 0; j < 4; ++j) acc2[i][j] = 0ULL;   // (0.f, 0.f)

#pragma unroll 4
    for (int d4 = 0; d4 < D4v; ++d4) {
        ulonglong2 xv[4], tv[4];
#pragma unroll
        for (int i = 0; i < 4; ++i)
            xv[i] = *reinterpret_cast<const ulonglong2*>(&xs[p][xsw(c + 4 * i, d4)]);
#pragma unroll
        for (int j = 0; j < 4; ++j)
            tv[j] = *reinterpret_cast<const ulonglong2*>(&ts[p][tsw(r + 16 * j, d4)]);
#pragma unroll
        for (int i = 0; i < 4; ++i)
#pragma unroll
            for (int j = 0; j < 4; ++j) {
                acc2[i][j] = f2_fma(xv[i].x, tv[j].x, acc2[i][j]);
                acc2[i][j] = f2_fma(xv[i].y, tv[j].y, acc2[i][j]);
            }
    }

    // distances; per-thread min+argmin over its 4 k's per b
    float df[4][4];
    float bv[4];
    int   bk[4];
#pragma unroll
    for (int i = 0; i < 4; ++i) {
        const float bx2 = x2s[p][c + 4 * i];
        bv[i] = FLT_MAX; bk[i] = Kv;
#pragma unroll
        for (int j = 0; j < 4; ++j) {
            const int k = r + 16 * j;
            float lo, hi;
            f2_unpack(acc2[i][j], lo, hi);
            const float d = bx2 + t2s[p][k] - 2.0f * (lo + hi);
            df[i][j] = d;
            if (d < bv[i]) { bv[i] = d; bk[i] = k; }  // j asc => first-min
        }
    }

    // ---- shuffle reduce across the 8 r's within this warp (lane = 4r+c) ----
#pragma unroll
    for (int m = 4; m <= 16; m <<= 1) {
#pragma unroll
        for (int i = 0; i < 4; ++i) {
            const float ov = __shfl_xor_sync(0xFFFFFFFFu, bv[i], m);
            const int   ok = __shfl_xor_sync(0xFFFFFFFFu, bk[i], m);
            if (ov < bv[i] || (ov == bv[i] && ok < bk[i])) { bv[i] = ov; bk[i] = ok; }
        }
    }
    const int half = q >> 5;             // warp-in-pixel: r<8 -> 0, r>=8 -> 1
    if ((r & 7) == 0) {                  // lanes 0..3 of each warp
#pragma unroll
        for (int i = 0; i < 4; ++i) {
            rv2[p][half][c + 4 * i] = bv[i];
            ri2[p][half][c + 4 * i] = bk[i];
        }
    }
    __syncthreads();

    // ---- cross-warp merge per b (q<16) ----
    if (q < Bv) {
        float v0 = rv2[p][0][q]; int k0 = ri2[p][0][q];
        const float v1 = rv2[p][1][q]; const int k1 = ri2[p][1][q];
        if (v1 < v0 || (v1 == v0 && k1 < k0)) { v0 = v1; k0 = k1; }
        bestvs[p][q] = v0;
        bestks[p][q] = k0;
    }
    __syncthreads();

    // ---- near-tie candidate count per b ----
#pragma unroll
    for (int i = 0; i < 4; ++i) {
        const int b = c + 4 * i;
        const float lim = bestvs[p][b] + EPS;
        int local = 0;
#pragma unroll
        for (int j = 0; j < 4; ++j) local += (df[i][j] <= lim) ? 1 : 0;
        if (local) atomicAdd(&cnt[p][b], local);
    }
    __syncthreads();

    // ---- Phase B (RARE): exact fp64 refinement for contested b ----
#pragma unroll
    for (int i = 0; i < 4; ++i) {
        const int b = c + 4 * i;
        if (cnt[p][b] < 2) continue;                  // uncontested: skip fp64
        const float lim = bestvs[p][b] + EPS;
#pragma unroll
        for (int j = 0; j < 4; ++j) {
            if (df[i][j] > lim) continue;
            const int k = r + 16 * j;
            double dd = 0.0;
#pragma unroll 1
            for (int d4 = 0; d4 < D4v; ++d4) {
                const float4 xv = xs[p][xsw(b, d4)];
                const float4 tv = ts[p][tsw(k, d4)];
                const double e0 = (double)xv.x - (double)tv.x;
                const double e1 = (double)xv.y - (double)tv.y;
                const double e2 = (double)xv.z - (double)tv.z;
                const double e3 = (double)xv.w - (double)tv.w;
                dd = fma(e0, e0, dd); dd = fma(e1, e1, dd);
                dd = fma(e2, e2, dd); dd = fma(e3, e3, dd);
            }
            const float dfx = (float)dd;              // exact -> fp32
            const ull key = ((ull)__float_as_uint(dfx) << 6) | (ull)k;
            atomicMin(&refined[p][b], key);
        }
    }
    __syncthreads();

    // ---- finalize per (pixel, b): threads 0..31 ----
    if (tid < PPB * Bv) {
        const int pp = tid >> 4;
        const int b  = tid & 15;
        float fbv; int fbk;
        if (cnt[pp][b] >= 2) {
            const ull key = refined[pp][b];
            fbk = (int)(key & 63ULL);
            fbv = __uint_as_float((unsigned)(key >> 6));
        } else {
            fbv = bestvs[pp][b];
            fbk = bestks[pp][b];
        }
        fin_v[pp][b]   = fbv;
        fin_cls[pp][b] = clsf[fbk];
    }
    __syncthreads();

    // ---- epilogue: 64 threads, one (output, b) each; float2 over 2 pixels ----
    if (tid < 4 * Bv) {
        const int o = tid >> 4;
        const int b = tid & 15;
        const float v0 = fin_v[0][b];
        const float v1 = fin_v[1][b];
        float2 val;
        if      (o == 0) val = make_float2(v0 <= 0.5f ? 1.f : 0.f, v1 <= 0.5f ? 1.f : 0.f);
        else if (o == 1) val = make_float2(v0 <= 1.0f ? 1.f : 0.f, v1 <= 1.0f ? 1.f : 0.f);
        else if (o == 2) val = make_float2(v0, v1);
        else             val = make_float2(fin_cls[0][b], fin_cls[1][b]);
        const size_t BN = (size_t)Bv * Nv;
        *reinterpret_cast<float2*>(&out[(size_t)o * BN + (size_t)b * Nv + n0]) = val;
    }
}

extern "C" void kernel_launch(void* const* d_in, const int* in_sizes, int n_in,
                              void* d_out, int out_size)
{
    const float4* frame = (const float4*)d_in[0];   // [16,16384,64] f32
    const float4* tmpl  = (const float4*)d_in[1];   // [64,16384,64] f32
    const int*    tcls  = (const int*)d_in[2];      // [64] int32
    float*        out   = (float*)d_out;

    osc_kernel<<<Nv / PPB, 64 * PPB>>>(frame, tmpl, tcls, out);
}